// round 13
// baseline (speedup 1.0000x reference)
#include <cuda_runtime.h>
#include <cuda_bf16.h>
#include <mma.h>
#include <cstdint>

using namespace nvcuda;

#define B_  256
#define H_  1024
#define L_  128
#define V_  32000

// ---------------- scratch (device globals) ----------------
__device__ float g_xcat[B_ * 2 * H_];
__device__ float g_x   [B_ * H_];
__device__ float g_gx  [B_ * 3 * H_];
__device__ float g_gh  [B_ * 3 * H_];
__device__ __nv_bfloat16 g_hb[B_ * H_];       // bf16 h_new
__device__ __nv_bfloat16 g_wb[(size_t)V_ * H_];  // bf16 out_w (per-call convert)

// output layout: [logp (256x32000) | h_new (256x1024) | attn_weights (256x128)]
#define OFF_H    (B_ * V_)
#define OFF_ATTN (OFF_H + B_ * H_)

__device__ __forceinline__ uint2 cvt_f4_bf16(float4 v) {
    uint2 u;
    asm("cvt.rn.bf16x2.f32 %0, %1, %2;" : "=r"(u.x) : "f"(v.y), "f"(v.x));
    asm("cvt.rn.bf16x2.f32 %0, %1, %2;" : "=r"(u.y) : "f"(v.w), "f"(v.z));
    return u;
}
__device__ __forceinline__ uint32_t smem_u32(const void* p) {
    uint32_t a;
    asm("{ .reg .u64 t; cvta.to.shared.u64 t, %1; cvt.u32.u64 %0, t; }" : "=r"(a) : "l"(p));
    return a;
}
__device__ __forceinline__ void cp16(uint32_t d, const void* s) {
    asm volatile("cp.async.cg.shared.global [%0], [%1], 16;" :: "r"(d), "l"(s));
}
#define CP_COMMIT() asm volatile("cp.async.commit_group;" ::: "memory")
#define CP_WAIT2()  asm volatile("cp.async.wait_group 2;" ::: "memory")

// ====================================================================
// K0: W fp32 -> bf16 (side stream, hidden under main chain)
// ====================================================================
__global__ __launch_bounds__(256)
void convert_w_kernel(const float* __restrict__ W, __nv_bfloat16* __restrict__ Wb) {
    const size_t i = ((size_t)blockIdx.x * 256 + threadIdx.x) * 8;
    const float4 v0 = *(const float4*)&W[i];
    const float4 v1 = *(const float4*)&W[i + 4];
    const uint2 a = cvt_f4_bf16(v0), b = cvt_f4_bf16(v1);
    *(uint4*)&Wb[i] = make_uint4(a.x, a.y, b.x, b.y);
}

// ====================================================================
// K1: attention (gather + logits + softmax + einsum)
// ====================================================================
__global__ void attn_kernel(const int* __restrict__ ids,
                            const float* __restrict__ hidden,
                            const float* __restrict__ enc,
                            const float* __restrict__ emb,
                            const float* __restrict__ attn_w,
                            const float* __restrict__ attn_b,
                            float* __restrict__ attn_out,
                            float* __restrict__ xcat) {
    __shared__ float sx[2 * H_];
    __shared__ float sw[L_];
    __shared__ float sred[256];

    const int b = blockIdx.x;
    const int tid = threadIdx.x;
    const int id = ids[b];

    for (int i = tid; i < H_; i += 256) {
        sx[i]      = emb[id * H_ + i];
        sx[H_ + i] = hidden[b * H_ + i];
    }
    __syncthreads();

    const int warp = tid >> 5, lane = tid & 31;
    for (int l = warp; l < L_; l += 8) {
        const float* wr = attn_w + l * (2 * H_);
        float s = 0.f;
        #pragma unroll 8
        for (int k = lane; k < 2 * H_; k += 32) s += sx[k] * wr[k];
        #pragma unroll
        for (int o = 16; o; o >>= 1) s += __shfl_down_sync(0xffffffffu, s, o);
        if (lane == 0) sw[l] = s + attn_b[l];
    }
    __syncthreads();

    sred[tid] = (tid < L_) ? sw[tid] : -1e30f;
    __syncthreads();
    #pragma unroll
    for (int s2 = 128; s2 >= 1; s2 >>= 1) {
        if (tid < s2) sred[tid] = fmaxf(sred[tid], sred[tid + s2]);
        __syncthreads();
    }
    const float m = sred[0];
    __syncthreads();
    float e = 0.f;
    if (tid < L_) e = expf(sw[tid] - m);
    sred[tid] = e;
    __syncthreads();
    #pragma unroll
    for (int s2 = 128; s2 >= 1; s2 >>= 1) {
        if (tid < s2) sred[tid] += sred[tid + s2];
        __syncthreads();
    }
    const float inv = 1.0f / sred[0];
    __syncthreads();
    if (tid < L_) {
        const float w = e * inv;
        sw[tid] = w;
        attn_out[b * L_ + tid] = w;
    }
    __syncthreads();

    const float* eb = enc + (size_t)b * L_ * H_;
    float a0 = 0.f, a1 = 0.f, a2 = 0.f, a3 = 0.f;
    #pragma unroll 4
    for (int l = 0; l < L_; ++l) {
        const float w = sw[l];
        const float* p = eb + l * H_ + tid;
        a0 = fmaf(w, p[0],   a0);
        a1 = fmaf(w, p[256], a1);
        a2 = fmaf(w, p[512], a2);
        a3 = fmaf(w, p[768], a3);
    }
    float* xc = xcat + b * 2 * H_;
    xc[tid]        = sx[tid];
    xc[tid + 256]  = sx[tid + 256];
    xc[tid + 512]  = sx[tid + 512];
    xc[tid + 768]  = sx[tid + 768];
    xc[H_ + tid]       = a0;
    xc[H_ + tid + 256] = a1;
    xc[H_ + tid + 512] = a2;
    xc[H_ + tid + 768] = a3;
}

// ====================================================================
// init: gh = b_hh, gx = b_ih, x = comb_b (broadcast over rows)
// ====================================================================
__global__ void init_bias_kernel(float* __restrict__ gh, const float* __restrict__ b_hh,
                                 float* __restrict__ gx, const float* __restrict__ b_ih,
                                 float* __restrict__ x,  const float* __restrict__ comb_b) {
    const int i = blockIdx.x * 256 + threadIdx.x;
    const int n3 = i % (3 * H_);
    gh[i] = b_hh[n3];
    gx[i] = b_ih[n3];
    if (i < B_ * H_) x[i] = comb_b[i & (H_ - 1)];
}

// ====================================================================
// split-K tf32 GEMM: C += A[M,k0:k0+kspan] @ W[N, k0:]^T  (atomicAdd)
// ====================================================================
#define TLD 40
#define TLDC 72

__global__ __launch_bounds__(128)
void gemm_tf32_splitk(const float* __restrict__ A,
                      const float* __restrict__ W,
                      float* __restrict__ C,
                      int K, int kspan, int N, int relu_a) {
    __shared__ __align__(16) float As[2][64 * TLD];
    __shared__ __align__(16) float Bs[2][64 * TLD];

    const int n0 = blockIdx.x * 64;
    const int m0 = blockIdx.y * 64;
    const int k0 = blockIdx.z * kspan;
    const int tid = threadIdx.x;
    const int warp = tid >> 5;
    const int wm = warp >> 1, wn = warp & 1;
    const int lr = tid >> 3;
    const int lc = (tid & 7) * 4;

    wmma::fragment<wmma::accumulator, 16, 16, 8, float> c[2][2];
    #pragma unroll
    for (int i = 0; i < 2; i++)
        #pragma unroll
        for (int j = 0; j < 2; j++) wmma::fill_fragment(c[i][j], 0.0f);

    float4 ra[4], rb[4];
    #pragma unroll
    for (int i = 0; i < 4; i++) {
        ra[i] = *(const float4*)&A[(size_t)(m0 + lr + i * 16) * K + k0 + lc];
        rb[i] = *(const float4*)&W[(size_t)(n0 + lr + i * 16) * K + k0 + lc];
    }
    if (relu_a) {
        #pragma unroll
        for (int i = 0; i < 4; i++) {
            ra[i].x = fmaxf(ra[i].x, 0.f); ra[i].y = fmaxf(ra[i].y, 0.f);
            ra[i].z = fmaxf(ra[i].z, 0.f); ra[i].w = fmaxf(ra[i].w, 0.f);
        }
    }

    const int NT = kspan >> 5;
    for (int kt = 0; kt < NT; kt++) {
        const int cur = kt & 1;
        #pragma unroll
        for (int i = 0; i < 4; i++) {
            *(float4*)&As[cur][(lr + i * 16) * TLD + lc] = ra[i];
            *(float4*)&Bs[cur][(lr + i * 16) * TLD + lc] = rb[i];
        }
        __syncthreads();
        if (kt + 1 < NT) {
            const int ko = k0 + (kt + 1) * 32 + lc;
            #pragma unroll
            for (int i = 0; i < 4; i++) {
                ra[i] = *(const float4*)&A[(size_t)(m0 + lr + i * 16) * K + ko];
                rb[i] = *(const float4*)&W[(size_t)(n0 + lr + i * 16) * K + ko];
            }
            if (relu_a) {
                #pragma unroll
                for (int i = 0; i < 4; i++) {
                    ra[i].x = fmaxf(ra[i].x, 0.f); ra[i].y = fmaxf(ra[i].y, 0.f);
                    ra[i].z = fmaxf(ra[i].z, 0.f); ra[i].w = fmaxf(ra[i].w, 0.f);
                }
            }
        }
        #pragma unroll
        for (int kk = 0; kk < 4; kk++) {
            wmma::fragment<wmma::matrix_a, 16, 16, 8, wmma::precision::tf32, wmma::row_major> a[2];
            wmma::fragment<wmma::matrix_b, 16, 16, 8, wmma::precision::tf32, wmma::col_major> bf[2];
            #pragma unroll
            for (int i = 0; i < 2; i++) {
                wmma::load_matrix_sync(a[i], &As[cur][(wm * 32 + i * 16) * TLD + kk * 8], TLD);
                #pragma unroll
                for (int t = 0; t < a[i].num_elements; t++)
                    a[i].x[t] = wmma::__float_to_tf32(a[i].x[t]);
            }
            #pragma unroll
            for (int j = 0; j < 2; j++) {
                wmma::load_matrix_sync(bf[j], &Bs[cur][(wn * 32 + j * 16) * TLD + kk * 8], TLD);
                #pragma unroll
                for (int t = 0; t < bf[j].num_elements; t++)
                    bf[j].x[t] = wmma::__float_to_tf32(bf[j].x[t]);
            }
            #pragma unroll
            for (int i = 0; i < 2; i++)
                #pragma unroll
                for (int j = 0; j < 2; j++)
                    wmma::mma_sync(c[i][j], a[i], bf[j], c[i][j]);
        }
    }

    __syncthreads();
    float* Cs = (float*)As;
    #pragma unroll
    for (int i = 0; i < 2; i++)
        #pragma unroll
        for (int j = 0; j < 2; j++)
            wmma::store_matrix_sync(&Cs[(wm * 32 + i * 16) * TLDC + wn * 32 + j * 16],
                                    c[i][j], TLDC, wmma::mem_row_major);
    __syncthreads();
    for (int i = tid; i < 64 * 64; i += 128) {
        const int mm = i >> 6, nn = i & 63;
        atomicAdd(&C[(size_t)(m0 + mm) * N + n0 + nn], Cs[mm * TLDC + nn]);
    }
}

// ====================================================================
// K4: GRU gates (emits fp32 h_new output + bf16 copy)
// ====================================================================
__global__ void gru_gate_kernel(const float* __restrict__ gx,
                                const float* __restrict__ gh,
                                const float* __restrict__ hidden,
                                float* __restrict__ hout,
                                __nv_bfloat16* __restrict__ hb) {
    const int idx = blockIdx.x * blockDim.x + threadIdx.x;
    const int b = idx >> 10, j = idx & (H_ - 1);
    const float* gxb = gx + b * 3 * H_;
    const float* ghb = gh + b * 3 * H_;
    const float xr = gxb[j],          hr = ghb[j];
    const float xz = gxb[H_ + j],     hz = ghb[H_ + j];
    const float xn = gxb[2 * H_ + j], hn = ghb[2 * H_ + j];
    const float r = 1.0f / (1.0f + expf(-(xr + hr)));
    const float z = 1.0f / (1.0f + expf(-(xz + hz)));
    const float n = tanhf(xn + r * hn);
    const float h = (1.0f - z) * n + z * hidden[idx];
    hout[idx] = h;
    hb[idx] = __float2bfloat16(h);
}

// ====================================================================
// K5: bf16 vocab GEMM  logits[B,V] = hb[B,H] @ wb[V,H]^T   (all bf16 in)
// BM=256 (W streamed once), BN=128, BK=32, 512 threads, 16 warps (4x4),
// cp.async 4-stage ring, 3-deep prefetch, one sync per k-iter.
// ====================================================================
#define VLD 40                        // bf16 leading dim (80B rows)
#define VAS (256 * VLD)               // A stage elems
#define VBS (128 * VLD)               // B stage elems
#define VSTG 4
#define VOC_SMEM ((VSTG * (VAS + VBS)) * 2)   // 122880 bytes

__global__ __launch_bounds__(512)
void gemm_bf16_vocab(const __nv_bfloat16* __restrict__ A,
                     const __nv_bfloat16* __restrict__ W,
                     float* __restrict__ C) {
    extern __shared__ __align__(16) __nv_bfloat16 sm[];
    __nv_bfloat16* As = sm;               // [VSTG][VAS]
    __nv_bfloat16* Bs = sm + VSTG * VAS;  // [VSTG][VBS]
    const uint32_t as_u = smem_u32(As);
    const uint32_t bs_u = smem_u32(Bs);

    const int n0 = blockIdx.x * 128;
    const int tid = threadIdx.x;
    const int warp = tid >> 5;
    const int wm = warp >> 2;          // 0..3 (64 rows each)
    const int wn = warp & 3;           // 0..3 (32 cols each)
    // A: 256 rows x 32 cols bf16 per stage = 1024 x 16B; 2 chunks/thread
    const int arow = tid >> 1;         // 0..255
    const int acol = (tid & 1) * 16;   // 0 / 16 (elems)
    // W: 128 rows x 32 cols bf16 per stage = 512 x 16B; 1 chunk/thread
    const int wrow = tid >> 2;         // 0..127
    const int wcol = (tid & 3) * 8;    // 0/8/16/24 (elems)

    wmma::fragment<wmma::accumulator, 16, 16, 16, float> c[4][2];
    #pragma unroll
    for (int i = 0; i < 4; i++)
        #pragma unroll
        for (int j = 0; j < 2; j++) wmma::fill_fragment(c[i][j], 0.0f);

    const __nv_bfloat16* Arow = A + (size_t)arow * H_ + acol;
    const __nv_bfloat16* Wrow = W + (size_t)(n0 + wrow) * H_ + wcol;
    const uint32_t a_dst = as_u + (uint32_t)(arow * VLD + acol) * 2;
    const uint32_t b_dst = bs_u + (uint32_t)(wrow * VLD + wcol) * 2;

    // prologue: stages 0..2
    #pragma unroll
    for (int s = 0; s < 3; s++) {
        const int kc = s * 32;
        cp16(a_dst + (uint32_t)(s * VAS) * 2,      Arow + kc);
        cp16(a_dst + (uint32_t)(s * VAS) * 2 + 16, Arow + kc + 8);
        cp16(b_dst + (uint32_t)(s * VBS) * 2,      Wrow + kc);
        CP_COMMIT();
    }

    const int NT = H_ / 32;   // 32
    for (int kt = 0; kt < NT; kt++) {
        const int cur = kt & 3;
        CP_WAIT2();
        __syncthreads();

        const __nv_bfloat16* Ac = As + cur * VAS;
        const __nv_bfloat16* Bc = Bs + cur * VBS;
        #pragma unroll
        for (int kk = 0; kk < 2; kk++) {
            wmma::fragment<wmma::matrix_a, 16, 16, 16, __nv_bfloat16, wmma::row_major> a[4];
            wmma::fragment<wmma::matrix_b, 16, 16, 16, __nv_bfloat16, wmma::col_major> bf[2];
            #pragma unroll
            for (int i = 0; i < 4; i++)
                wmma::load_matrix_sync(a[i], &Ac[(wm * 64 + i * 16) * VLD + kk * 16], VLD);
            #pragma unroll
            for (int j = 0; j < 2; j++)
                wmma::load_matrix_sync(bf[j], &Bc[(wn * 32 + j * 16) * VLD + kk * 16], VLD);
            #pragma unroll
            for (int i = 0; i < 4; i++)
                #pragma unroll
                for (int j = 0; j < 2; j++)
                    wmma::mma_sync(c[i][j], a[i], bf[j], c[i][j]);
        }

        // issue stage kt+3
        if (kt + 3 < NT) {
            const int s = (kt + 3) & 3;
            const int kc = (kt + 3) * 32;
            cp16(a_dst + (uint32_t)(s * VAS) * 2,      Arow + kc);
            cp16(a_dst + (uint32_t)(s * VAS) * 2 + 16, Arow + kc + 8);
            cp16(b_dst + (uint32_t)(s * VBS) * 2,      Wrow + kc);
        }
        CP_COMMIT();
    }

    #pragma unroll
    for (int i = 0; i < 4; i++)
        #pragma unroll
        for (int j = 0; j < 2; j++)
            wmma::store_matrix_sync(&C[(size_t)(wm * 64 + i * 16) * V_ + n0 + wn * 32 + j * 16],
                                    c[i][j], V_, wmma::mem_row_major);
}

// ====================================================================
// K6: bias + log_softmax (row in registers)
// ====================================================================
__global__ __launch_bounds__(1024)
void logsoftmax_kernel(float* __restrict__ logits,
                       const float* __restrict__ ob) {
    __shared__ float sred[32];
    const int b = blockIdx.x;
    const int tid = threadIdx.x;
    const int lane = tid & 31, wid = tid >> 5;
    float* row = logits + (size_t)b * V_;

    float v[32];
    float m = -1e30f;
    #pragma unroll
    for (int k = 0; k < 32; k++) {
        const int idx = k * 1024 + tid;
        float t = -1e30f;
        if (idx < V_) t = row[idx] + ob[idx];
        v[k] = t;
        m = fmaxf(m, t);
    }
    #pragma unroll
    for (int o = 16; o; o >>= 1) m = fmaxf(m, __shfl_xor_sync(0xffffffffu, m, o));
    if (lane == 0) sred[wid] = m;
    __syncthreads();
    if (wid == 0) {
        float t = sred[lane];
        #pragma unroll
        for (int o = 16; o; o >>= 1) t = fmaxf(t, __shfl_xor_sync(0xffffffffu, t, o));
        if (lane == 0) sred[0] = t;
    }
    __syncthreads();
    m = sred[0];
    __syncthreads();

    float s = 0.f;
    #pragma unroll
    for (int k = 0; k < 32; k++) {
        const int idx = k * 1024 + tid;
        if (idx < V_) {
            v[k] = v[k] - m;
            s += expf(v[k]);
        }
    }
    #pragma unroll
    for (int o = 16; o; o >>= 1) s += __shfl_xor_sync(0xffffffffu, s, o);
    if (lane == 0) sred[wid] = s;
    __syncthreads();
    if (wid == 0) {
        float t = sred[lane];
        #pragma unroll
        for (int o = 16; o; o >>= 1) t += __shfl_xor_sync(0xffffffffu, t, o);
        if (lane == 0) sred[0] = t;
    }
    __syncthreads();
    const float lse = logf(sred[0]);

    #pragma unroll
    for (int k = 0; k < 32; k++) {
        const int idx = k * 1024 + tid;
        if (idx < V_) row[idx] = v[k] - lse;
    }
}

// ====================================================================
extern "C" void kernel_launch(void* const* d_in, const int* in_sizes, int n_in,
                              void* d_out, int out_size) {
    const int*   ids    = (const int*)  d_in[0];
    const float* hidden = (const float*)d_in[1];
    const float* enc    = (const float*)d_in[2];
    const float* emb    = (const float*)d_in[3];
    const float* attn_w = (const float*)d_in[4];
    const float* attn_b = (const float*)d_in[5];
    const float* comb_w = (const float*)d_in[6];
    const float* comb_b = (const float*)d_in[7];
    const float* w_ih   = (const float*)d_in[8];
    const float* b_ih   = (const float*)d_in[9];
    const float* w_hh   = (const float*)d_in[10];
    const float* b_hh   = (const float*)d_in[11];
    const float* out_w  = (const float*)d_in[12];
    const float* out_b  = (const float*)d_in[13];

    float* out      = (float*)d_out;
    float* out_logp = out;
    float* out_h    = out + OFF_H;
    float* out_attn = out + OFF_ATTN;

    float *xcat, *x, *gx, *gh;
    __nv_bfloat16 *hb, *wb;
    cudaGetSymbolAddress((void**)&xcat, g_xcat);
    cudaGetSymbolAddress((void**)&x,    g_x);
    cudaGetSymbolAddress((void**)&gx,   g_gx);
    cudaGetSymbolAddress((void**)&gh,   g_gh);
    cudaGetSymbolAddress((void**)&hb,   g_hb);
    cudaGetSymbolAddress((void**)&wb,   g_wb);

    cudaFuncSetAttribute(gemm_bf16_vocab,
                         cudaFuncAttributeMaxDynamicSharedMemorySize, VOC_SMEM);

    static cudaStream_t s_side = nullptr;
    static cudaEvent_t ev_fork = nullptr, ev_w = nullptr;
    if (!s_side) {
        cudaStreamCreateWithFlags(&s_side, cudaStreamNonBlocking);
        cudaEventCreateWithFlags(&ev_fork, cudaEventDisableTiming);
        cudaEventCreateWithFlags(&ev_w,    cudaEventDisableTiming);
    }

    // side: convert out_w -> bf16 (hidden under the whole main chain)
    cudaEventRecord(ev_fork, 0);
    cudaStreamWaitEvent(s_side, ev_fork, 0);
    convert_w_kernel<<<(V_ * (H_ / 8)) / 256, 256, 0, s_side>>>(out_w, wb);
    cudaEventRecord(ev_w, s_side);

    // main chain
    init_bias_kernel<<<B_ * 3 * H_ / 256, 256>>>(gh, b_hh, gx, b_ih, x, comb_b);
    attn_kernel<<<B_, 256>>>(ids, hidden, enc, emb, attn_w, attn_b, out_attn, xcat);
    gemm_tf32_splitk<<<dim3(48, 4, 8), 128>>>(hidden, w_hh, gh, H_, 128, 3 * H_, 0);
    gemm_tf32_splitk<<<dim3(16, 4, 16), 128>>>(xcat, comb_w, x, 2 * H_, 128, H_, 0);
    gemm_tf32_splitk<<<dim3(48, 4, 8), 128>>>(x, w_ih, gx, H_, 128, 3 * H_, 1);
    gru_gate_kernel<<<B_ * H_ / 256, 256>>>(gx, gh, hidden, out_h, hb);

    // join: vocab needs bf16 W from the side stream
    cudaStreamWaitEvent(0, ev_w, 0);
    gemm_bf16_vocab<<<V_ / 128, 512, VOC_SMEM>>>(hb, wb, out_logp);
    logsoftmax_kernel<<<B_, 1024>>>(out_logp, out_b);
}

// round 14
// speedup vs baseline: 1.0975x; 1.0975x over previous
#include <cuda_runtime.h>
#include <cuda_bf16.h>
#include <mma.h>
#include <cstdint>

using namespace nvcuda;

#define B_  256
#define H_  1024
#define L_  128
#define V_  32000

// ---------------- scratch (device globals) ----------------
__device__ float g_xcat[B_ * 2 * H_];
__device__ float g_x   [B_ * H_];
__device__ float g_gx  [B_ * 3 * H_];
__device__ float g_gh  [B_ * 3 * H_];

// output layout: [logp (256x32000) | h_new (256x1024) | attn_weights (256x128)]
#define OFF_H    (B_ * V_)
#define OFF_ATTN (OFF_H + B_ * H_)

// fp32x4 -> packed bf16x2 pair via PTX cvt
__device__ __forceinline__ uint2 cvt_f4_bf16(float4 v) {
    uint2 u;
    asm("cvt.rn.bf16x2.f32 %0, %1, %2;" : "=r"(u.x) : "f"(v.y), "f"(v.x));
    asm("cvt.rn.bf16x2.f32 %0, %1, %2;" : "=r"(u.y) : "f"(v.w), "f"(v.z));
    return u;
}

// ====================================================================
// K1: attention (gather + logits + softmax + einsum)
// einsum now uses one LDG.128 per thread per l (vs 4 scalar LDG.32)
// ====================================================================
__global__ void attn_kernel(const int* __restrict__ ids,
                            const float* __restrict__ hidden,
                            const float* __restrict__ enc,
                            const float* __restrict__ emb,
                            const float* __restrict__ attn_w,
                            const float* __restrict__ attn_b,
                            float* __restrict__ attn_out,
                            float* __restrict__ xcat) {
    __shared__ float sx[2 * H_];
    __shared__ float sw[L_];
    __shared__ float sred[256];

    const int b = blockIdx.x;
    const int tid = threadIdx.x;
    const int id = ids[b];

    for (int i = tid; i < H_; i += 256) {
        sx[i]      = emb[id * H_ + i];
        sx[H_ + i] = hidden[b * H_ + i];
    }
    __syncthreads();

    const int warp = tid >> 5, lane = tid & 31;
    for (int l = warp; l < L_; l += 8) {
        const float* wr = attn_w + l * (2 * H_);
        float s = 0.f;
        #pragma unroll 8
        for (int k = lane; k < 2 * H_; k += 32) s += sx[k] * wr[k];
        #pragma unroll
        for (int o = 16; o; o >>= 1) s += __shfl_down_sync(0xffffffffu, s, o);
        if (lane == 0) sw[l] = s + attn_b[l];
    }
    __syncthreads();

    sred[tid] = (tid < L_) ? sw[tid] : -1e30f;
    __syncthreads();
    #pragma unroll
    for (int s2 = 128; s2 >= 1; s2 >>= 1) {
        if (tid < s2) sred[tid] = fmaxf(sred[tid], sred[tid + s2]);
        __syncthreads();
    }
    const float m = sred[0];
    __syncthreads();
    float e = 0.f;
    if (tid < L_) e = expf(sw[tid] - m);
    sred[tid] = e;
    __syncthreads();
    #pragma unroll
    for (int s2 = 128; s2 >= 1; s2 >>= 1) {
        if (tid < s2) sred[tid] += sred[tid + s2];
        __syncthreads();
    }
    const float inv = 1.0f / sred[0];
    __syncthreads();
    if (tid < L_) {
        const float w = e * inv;
        sw[tid] = w;
        attn_out[b * L_ + tid] = w;
    }
    __syncthreads();

    // einsum: thread owns 4 contiguous cols; 1 x LDG.128 per l
    const float* eb = enc + (size_t)b * L_ * H_;
    const int col = tid * 4;
    float a0 = 0.f, a1 = 0.f, a2 = 0.f, a3 = 0.f;
    #pragma unroll 4
    for (int l = 0; l < L_; ++l) {
        const float w = sw[l];
        const float4 v = *(const float4*)(eb + (size_t)l * H_ + col);
        a0 = fmaf(w, v.x, a0);
        a1 = fmaf(w, v.y, a1);
        a2 = fmaf(w, v.z, a2);
        a3 = fmaf(w, v.w, a3);
    }
    float* xc = xcat + b * 2 * H_;
    *(float4*)(xc + col)      = *(const float4*)(sx + col);
    *(float4*)(xc + H_ + col) = make_float4(a0, a1, a2, a3);
}

// ====================================================================
// init: gh = b_hh, gx = b_ih, x = comb_b (broadcast over rows)
// ====================================================================
__global__ void init_bias_kernel(float* __restrict__ gh, const float* __restrict__ b_hh,
                                 float* __restrict__ gx, const float* __restrict__ b_ih,
                                 float* __restrict__ x,  const float* __restrict__ comb_b) {
    const int i = blockIdx.x * 256 + threadIdx.x;     // up to B*3H
    const int n3 = i % (3 * H_);
    gh[i] = b_hh[n3];
    gx[i] = b_ih[n3];
    if (i < B_ * H_) x[i] = comb_b[i & (H_ - 1)];
}

// ====================================================================
// split-K tf32 GEMM: C += A[M,k0:k0+kspan] @ W[N, k0:]^T  (atomicAdd)
// BM=64 BN=64 BK=32, 128 threads, double-buffered, single sync per iter
// ====================================================================
#define TLD 40
#define TLDC 72

__global__ __launch_bounds__(128)
void gemm_tf32_splitk(const float* __restrict__ A,
                      const float* __restrict__ W,
                      float* __restrict__ C,
                      int K, int kspan, int N, int relu_a) {
    __shared__ __align__(16) float As[2][64 * TLD];
    __shared__ __align__(16) float Bs[2][64 * TLD];

    const int n0 = blockIdx.x * 64;
    const int m0 = blockIdx.y * 64;
    const int k0 = blockIdx.z * kspan;
    const int tid = threadIdx.x;
    const int warp = tid >> 5;
    const int wm = warp >> 1, wn = warp & 1;
    const int lr = tid >> 3;
    const int lc = (tid & 7) * 4;

    wmma::fragment<wmma::accumulator, 16, 16, 8, float> c[2][2];
    #pragma unroll
    for (int i = 0; i < 2; i++)
        #pragma unroll
        for (int j = 0; j < 2; j++) wmma::fill_fragment(c[i][j], 0.0f);

    float4 ra[4], rb[4];
    #pragma unroll
    for (int i = 0; i < 4; i++) {
        ra[i] = *(const float4*)&A[(size_t)(m0 + lr + i * 16) * K + k0 + lc];
        rb[i] = *(const float4*)&W[(size_t)(n0 + lr + i * 16) * K + k0 + lc];
    }
    if (relu_a) {
        #pragma unroll
        for (int i = 0; i < 4; i++) {
            ra[i].x = fmaxf(ra[i].x, 0.f); ra[i].y = fmaxf(ra[i].y, 0.f);
            ra[i].z = fmaxf(ra[i].z, 0.f); ra[i].w = fmaxf(ra[i].w, 0.f);
        }
    }

    const int NT = kspan >> 5;
    for (int kt = 0; kt < NT; kt++) {
        const int cur = kt & 1;
        #pragma unroll
        for (int i = 0; i < 4; i++) {
            *(float4*)&As[cur][(lr + i * 16) * TLD + lc] = ra[i];
            *(float4*)&Bs[cur][(lr + i * 16) * TLD + lc] = rb[i];
        }
        __syncthreads();
        if (kt + 1 < NT) {
            const int ko = k0 + (kt + 1) * 32 + lc;
            #pragma unroll
            for (int i = 0; i < 4; i++) {
                ra[i] = *(const float4*)&A[(size_t)(m0 + lr + i * 16) * K + ko];
                rb[i] = *(const float4*)&W[(size_t)(n0 + lr + i * 16) * K + ko];
            }
            if (relu_a) {
                #pragma unroll
                for (int i = 0; i < 4; i++) {
                    ra[i].x = fmaxf(ra[i].x, 0.f); ra[i].y = fmaxf(ra[i].y, 0.f);
                    ra[i].z = fmaxf(ra[i].z, 0.f); ra[i].w = fmaxf(ra[i].w, 0.f);
                }
            }
        }
        #pragma unroll
        for (int kk = 0; kk < 4; kk++) {
            wmma::fragment<wmma::matrix_a, 16, 16, 8, wmma::precision::tf32, wmma::row_major> a[2];
            wmma::fragment<wmma::matrix_b, 16, 16, 8, wmma::precision::tf32, wmma::col_major> bf[2];
            #pragma unroll
            for (int i = 0; i < 2; i++) {
                wmma::load_matrix_sync(a[i], &As[cur][(wm * 32 + i * 16) * TLD + kk * 8], TLD);
                #pragma unroll
                for (int t = 0; t < a[i].num_elements; t++)
                    a[i].x[t] = wmma::__float_to_tf32(a[i].x[t]);
            }
            #pragma unroll
            for (int j = 0; j < 2; j++) {
                wmma::load_matrix_sync(bf[j], &Bs[cur][(wn * 32 + j * 16) * TLD + kk * 8], TLD);
                #pragma unroll
                for (int t = 0; t < bf[j].num_elements; t++)
                    bf[j].x[t] = wmma::__float_to_tf32(bf[j].x[t]);
            }
            #pragma unroll
            for (int i = 0; i < 2; i++)
                #pragma unroll
                for (int j = 0; j < 2; j++)
                    wmma::mma_sync(c[i][j], a[i], bf[j], c[i][j]);
        }
    }

    __syncthreads();   // protect As before reuse as Cs
    float* Cs = (float*)As;
    #pragma unroll
    for (int i = 0; i < 2; i++)
        #pragma unroll
        for (int j = 0; j < 2; j++)
            wmma::store_matrix_sync(&Cs[(wm * 32 + i * 16) * TLDC + wn * 32 + j * 16],
                                    c[i][j], TLDC, wmma::mem_row_major);
    __syncthreads();
    for (int i = tid; i < 64 * 64; i += 128) {
        const int mm = i >> 6, nn = i & 63;
        atomicAdd(&C[(size_t)(m0 + mm) * N + n0 + nn], Cs[mm * TLDC + nn]);
    }
}

// ====================================================================
// K4: GRU gates
// ====================================================================
__global__ void gru_gate_kernel(const float* __restrict__ gx,
                                const float* __restrict__ gh,
                                const float* __restrict__ hidden,
                                float* __restrict__ hout) {
    const int idx = blockIdx.x * blockDim.x + threadIdx.x;
    const int b = idx >> 10, j = idx & (H_ - 1);
    const float* gxb = gx + b * 3 * H_;
    const float* ghb = gh + b * 3 * H_;
    const float xr = gxb[j],          hr = ghb[j];
    const float xz = gxb[H_ + j],     hz = ghb[H_ + j];
    const float xn = gxb[2 * H_ + j], hn = ghb[2 * H_ + j];
    const float r = 1.0f / (1.0f + expf(-(xr + hr)));
    const float z = 1.0f / (1.0f + expf(-(xz + hz)));
    const float n = tanhf(xn + r * hn);
    hout[idx] = (1.0f - z) * n + z * hidden[idx];
}

// ====================================================================
// K5: bf16 vocab GEMM  logits[B,V] = h_new[B,H] @ out_w[V,H]^T
// BM=256 (W streamed ONCE), BN=128, BK=32
// 512 threads = 16 warps (4x4), warp tile 64x32, double-buffered,
// SINGLE sync per k-iter  —  exact 303us-validated configuration
// ====================================================================
#define VLD 40                       // bf16 leading dim (80B rows)
#define VAS_STAGE (256 * VLD)        // elems per A stage
#define VBS_STAGE (128 * VLD)        // elems per B stage
#define VOC_SMEM ((2 * VAS_STAGE + 2 * VBS_STAGE) * 2)   // bytes = 61440

__global__ __launch_bounds__(512)
void gemm_bf16_vocab(const float* __restrict__ A,
                     const float* __restrict__ W,
                     float* __restrict__ C) {
    extern __shared__ __align__(16) __nv_bfloat16 sm[];
    __nv_bfloat16* As = sm;                     // [2][256*VLD]
    __nv_bfloat16* Bs = sm + 2 * VAS_STAGE;     // [2][128*VLD]

    const int n0 = blockIdx.x * 128;
    const int tid = threadIdx.x;
    const int warp = tid >> 5;
    const int wm = warp >> 2;        // 0..3 (64 rows each)
    const int wn = warp & 3;         // 0..3 (32 cols each)
    const int lr = tid >> 3;         // 0..63
    const int lc = (tid & 7) * 4;    // 0..28

    wmma::fragment<wmma::accumulator, 16, 16, 16, float> c[4][2];
    #pragma unroll
    for (int i = 0; i < 4; i++)
        #pragma unroll
        for (int j = 0; j < 2; j++) wmma::fill_fragment(c[i][j], 0.0f);

    float4 ra[4], rb[2];
    #pragma unroll
    for (int i = 0; i < 4; i++)
        ra[i] = *(const float4*)&A[(size_t)(lr + i * 64) * H_ + lc];
    #pragma unroll
    for (int i = 0; i < 2; i++)
        rb[i] = *(const float4*)&W[(size_t)(n0 + lr + i * 64) * H_ + lc];

    const int NT = H_ / 32;   // 32
    for (int kt = 0; kt < NT; kt++) {
        const int cur = kt & 1;
        #pragma unroll
        for (int i = 0; i < 4; i++)
            *(uint2*)&As[cur * VAS_STAGE + (lr + i * 64) * VLD + lc] = cvt_f4_bf16(ra[i]);
        #pragma unroll
        for (int i = 0; i < 2; i++)
            *(uint2*)&Bs[cur * VBS_STAGE + (lr + i * 64) * VLD + lc] = cvt_f4_bf16(rb[i]);
        __syncthreads();
        if (kt + 1 < NT) {
            const int ko = (kt + 1) * 32 + lc;
            #pragma unroll
            for (int i = 0; i < 4; i++)
                ra[i] = *(const float4*)&A[(size_t)(lr + i * 64) * H_ + ko];
            #pragma unroll
            for (int i = 0; i < 2; i++)
                rb[i] = *(const float4*)&W[(size_t)(n0 + lr + i * 64) * H_ + ko];
        }
        const __nv_bfloat16* Ac = As + cur * VAS_STAGE;
        const __nv_bfloat16* Bc = Bs + cur * VBS_STAGE;
        #pragma unroll
        for (int kk = 0; kk < 2; kk++) {
            wmma::fragment<wmma::matrix_a, 16, 16, 16, __nv_bfloat16, wmma::row_major> a[4];
            wmma::fragment<wmma::matrix_b, 16, 16, 16, __nv_bfloat16, wmma::col_major> bf[2];
            #pragma unroll
            for (int i = 0; i < 4; i++)
                wmma::load_matrix_sync(a[i], &Ac[(wm * 64 + i * 16) * VLD + kk * 16], VLD);
            #pragma unroll
            for (int j = 0; j < 2; j++)
                wmma::load_matrix_sync(bf[j], &Bc[(wn * 32 + j * 16) * VLD + kk * 16], VLD);
            #pragma unroll
            for (int i = 0; i < 4; i++)
                #pragma unroll
                for (int j = 0; j < 2; j++)
                    wmma::mma_sync(c[i][j], a[i], bf[j], c[i][j]);
        }
    }

    #pragma unroll
    for (int i = 0; i < 4; i++)
        #pragma unroll
        for (int j = 0; j < 2; j++)
            wmma::store_matrix_sync(&C[(size_t)(wm * 64 + i * 16) * V_ + n0 + wn * 32 + j * 16],
                                    c[i][j], V_, wmma::mem_row_major);
}

// ====================================================================
// K6: bias + log_softmax (row in registers)
// ====================================================================
__global__ __launch_bounds__(1024)
void logsoftmax_kernel(float* __restrict__ logits,
                       const float* __restrict__ ob) {
    __shared__ float sred[32];
    const int b = blockIdx.x;
    const int tid = threadIdx.x;
    const int lane = tid & 31, wid = tid >> 5;
    float* row = logits + (size_t)b * V_;

    float v[32];
    float m = -1e30f;
    #pragma unroll
    for (int k = 0; k < 32; k++) {
        const int idx = k * 1024 + tid;
        float t = -1e30f;
        if (idx < V_) t = row[idx] + ob[idx];
        v[k] = t;
        m = fmaxf(m, t);
    }
    #pragma unroll
    for (int o = 16; o; o >>= 1) m = fmaxf(m, __shfl_xor_sync(0xffffffffu, m, o));
    if (lane == 0) sred[wid] = m;
    __syncthreads();
    if (wid == 0) {
        float t = sred[lane];
        #pragma unroll
        for (int o = 16; o; o >>= 1) t = fmaxf(t, __shfl_xor_sync(0xffffffffu, t, o));
        if (lane == 0) sred[0] = t;
    }
    __syncthreads();
    m = sred[0];
    __syncthreads();

    float s = 0.f;
    #pragma unroll
    for (int k = 0; k < 32; k++) {
        const int idx = k * 1024 + tid;
        if (idx < V_) {
            v[k] = v[k] - m;
            s += expf(v[k]);
        }
    }
    #pragma unroll
    for (int o = 16; o; o >>= 1) s += __shfl_xor_sync(0xffffffffu, s, o);
    if (lane == 0) sred[wid] = s;
    __syncthreads();
    if (wid == 0) {
        float t = sred[lane];
        #pragma unroll
        for (int o = 16; o; o >>= 1) t += __shfl_xor_sync(0xffffffffu, t, o);
        if (lane == 0) sred[0] = t;
    }
    __syncthreads();
    const float lse = logf(sred[0]);

    #pragma unroll
    for (int k = 0; k < 32; k++) {
        const int idx = k * 1024 + tid;
        if (idx < V_) row[idx] = v[k] - lse;
    }
}

// ====================================================================
extern "C" void kernel_launch(void* const* d_in, const int* in_sizes, int n_in,
                              void* d_out, int out_size) {
    const int*   ids    = (const int*)  d_in[0];
    const float* hidden = (const float*)d_in[1];
    const float* enc    = (const float*)d_in[2];
    const float* emb    = (const float*)d_in[3];
    const float* attn_w = (const float*)d_in[4];
    const float* attn_b = (const float*)d_in[5];
    const float* comb_w = (const float*)d_in[6];
    const float* comb_b = (const float*)d_in[7];
    const float* w_ih   = (const float*)d_in[8];
    const float* b_ih   = (const float*)d_in[9];
    const float* w_hh   = (const float*)d_in[10];
    const float* b_hh   = (const float*)d_in[11];
    const float* out_w  = (const float*)d_in[12];
    const float* out_b  = (const float*)d_in[13];

    float* out      = (float*)d_out;
    float* out_logp = out;
    float* out_h    = out + OFF_H;
    float* out_attn = out + OFF_ATTN;

    float *xcat, *x, *gx, *gh;
    cudaGetSymbolAddress((void**)&xcat, g_xcat);
    cudaGetSymbolAddress((void**)&x,    g_x);
    cudaGetSymbolAddress((void**)&gx,   g_gx);
    cudaGetSymbolAddress((void**)&gh,   g_gh);

    cudaFuncSetAttribute(gemm_bf16_vocab,
                         cudaFuncAttributeMaxDynamicSharedMemorySize, VOC_SMEM);

    init_bias_kernel<<<B_ * 3 * H_ / 256, 256>>>(gh, b_hh, gx, b_ih, x, comb_b);
    attn_kernel<<<B_, 256>>>(ids, hidden, enc, emb, attn_w, attn_b, out_attn, xcat);
    // gh += hidden @ w_hh^T (split-K 8, kspan=128)
    gemm_tf32_splitk<<<dim3(48, 4, 8), 128>>>(hidden, w_hh, gh, H_, 128, 3 * H_, 0);
    // x += xcat @ comb_w^T (split-K 16, kspan=128)
    gemm_tf32_splitk<<<dim3(16, 4, 16), 128>>>(xcat, comb_w, x, 2 * H_, 128, H_, 0);
    // gx += relu(x) @ w_ih^T (split-K 8, kspan=128)
    gemm_tf32_splitk<<<dim3(48, 4, 8), 128>>>(x, w_ih, gx, H_, 128, 3 * H_, 1);
    gru_gate_kernel<<<B_ * H_ / 256, 256>>>(gx, gh, hidden, out_h);
    gemm_bf16_vocab<<<V_ / 128, 512, VOC_SMEM>>>(out_h, out_w, out_logp);
    logsoftmax_kernel<<<B_, 1024>>>(out_logp, out_b);
}

// round 15
// speedup vs baseline: 1.1150x; 1.0160x over previous
#include <cuda_runtime.h>
#include <cuda_bf16.h>
#include <mma.h>
#include <cstdint>

using namespace nvcuda;

#define B_  256
#define H_  1024
#define L_  128
#define V_  32000

// ---------------- scratch (device globals) ----------------
__device__ float g_xcat[B_ * 2 * H_];
__device__ float g_x   [B_ * H_];
__device__ float g_gx  [B_ * 3 * H_];
__device__ float g_gh  [B_ * 3 * H_];

// output layout: [logp (256x32000) | h_new (256x1024) | attn_weights (256x128)]
#define OFF_H    (B_ * V_)
#define OFF_ATTN (OFF_H + B_ * H_)

// fp32x4 -> packed bf16x2 pair via PTX cvt
__device__ __forceinline__ uint2 cvt_f4_bf16(float4 v) {
    uint2 u;
    asm("cvt.rn.bf16x2.f32 %0, %1, %2;" : "=r"(u.x) : "f"(v.y), "f"(v.x));
    asm("cvt.rn.bf16x2.f32 %0, %1, %2;" : "=r"(u.y) : "f"(v.w), "f"(v.z));
    return u;
}

// ====================================================================
// K1: attention (gather + logits + softmax + einsum)
// einsum: one LDG.128 per thread per l  (R14-validated)
// ====================================================================
__global__ void attn_kernel(const int* __restrict__ ids,
                            const float* __restrict__ hidden,
                            const float* __restrict__ enc,
                            const float* __restrict__ emb,
                            const float* __restrict__ attn_w,
                            const float* __restrict__ attn_b,
                            float* __restrict__ attn_out,
                            float* __restrict__ xcat) {
    __shared__ float sx[2 * H_];
    __shared__ float sw[L_];
    __shared__ float sred[256];

    const int b = blockIdx.x;
    const int tid = threadIdx.x;
    const int id = ids[b];

    for (int i = tid; i < H_; i += 256) {
        sx[i]      = emb[id * H_ + i];
        sx[H_ + i] = hidden[b * H_ + i];
    }
    __syncthreads();

    const int warp = tid >> 5, lane = tid & 31;
    for (int l = warp; l < L_; l += 8) {
        const float* wr = attn_w + l * (2 * H_);
        float s = 0.f;
        #pragma unroll 8
        for (int k = lane; k < 2 * H_; k += 32) s += sx[k] * wr[k];
        #pragma unroll
        for (int o = 16; o; o >>= 1) s += __shfl_down_sync(0xffffffffu, s, o);
        if (lane == 0) sw[l] = s + attn_b[l];
    }
    __syncthreads();

    sred[tid] = (tid < L_) ? sw[tid] : -1e30f;
    __syncthreads();
    #pragma unroll
    for (int s2 = 128; s2 >= 1; s2 >>= 1) {
        if (tid < s2) sred[tid] = fmaxf(sred[tid], sred[tid + s2]);
        __syncthreads();
    }
    const float m = sred[0];
    __syncthreads();
    float e = 0.f;
    if (tid < L_) e = expf(sw[tid] - m);
    sred[tid] = e;
    __syncthreads();
    #pragma unroll
    for (int s2 = 128; s2 >= 1; s2 >>= 1) {
        if (tid < s2) sred[tid] += sred[tid + s2];
        __syncthreads();
    }
    const float inv = 1.0f / sred[0];
    __syncthreads();
    if (tid < L_) {
        const float w = e * inv;
        sw[tid] = w;
        attn_out[b * L_ + tid] = w;
    }
    __syncthreads();

    const float* eb = enc + (size_t)b * L_ * H_;
    const int col = tid * 4;
    float a0 = 0.f, a1 = 0.f, a2 = 0.f, a3 = 0.f;
    #pragma unroll 4
    for (int l = 0; l < L_; ++l) {
        const float w = sw[l];
        const float4 v = *(const float4*)(eb + (size_t)l * H_ + col);
        a0 = fmaf(w, v.x, a0);
        a1 = fmaf(w, v.y, a1);
        a2 = fmaf(w, v.z, a2);
        a3 = fmaf(w, v.w, a3);
    }
    float* xc = xcat + b * 2 * H_;
    *(float4*)(xc + col)      = *(const float4*)(sx + col);
    *(float4*)(xc + H_ + col) = make_float4(a0, a1, a2, a3);
}

// ====================================================================
// init: gh = b_hh, gx = b_ih, x = comb_b (broadcast over rows)
// ====================================================================
__global__ void init_bias_kernel(float* __restrict__ gh, const float* __restrict__ b_hh,
                                 float* __restrict__ gx, const float* __restrict__ b_ih,
                                 float* __restrict__ x,  const float* __restrict__ comb_b) {
    const int i = blockIdx.x * 256 + threadIdx.x;     // up to B*3H
    const int n3 = i % (3 * H_);
    gh[i] = b_hh[n3];
    gx[i] = b_ih[n3];
    if (i < B_ * H_) x[i] = comb_b[i & (H_ - 1)];
}

// ====================================================================
// split-K tf32 GEMM: C += A[M,k0:k0+kspan] @ W[N, k0:]^T  (atomicAdd)
// BM=64 BN=64 BK=32, 128 threads, double-buffered, single sync per iter
// ====================================================================
#define TLD 40
#define TLDC 72

__global__ __launch_bounds__(128)
void gemm_tf32_splitk(const float* __restrict__ A,
                      const float* __restrict__ W,
                      float* __restrict__ C,
                      int K, int kspan, int N, int relu_a) {
    __shared__ __align__(16) float As[2][64 * TLD];
    __shared__ __align__(16) float Bs[2][64 * TLD];

    const int n0 = blockIdx.x * 64;
    const int m0 = blockIdx.y * 64;
    const int k0 = blockIdx.z * kspan;
    const int tid = threadIdx.x;
    const int warp = tid >> 5;
    const int wm = warp >> 1, wn = warp & 1;
    const int lr = tid >> 3;
    const int lc = (tid & 7) * 4;

    wmma::fragment<wmma::accumulator, 16, 16, 8, float> c[2][2];
    #pragma unroll
    for (int i = 0; i < 2; i++)
        #pragma unroll
        for (int j = 0; j < 2; j++) wmma::fill_fragment(c[i][j], 0.0f);

    float4 ra[4], rb[4];
    #pragma unroll
    for (int i = 0; i < 4; i++) {
        ra[i] = *(const float4*)&A[(size_t)(m0 + lr + i * 16) * K + k0 + lc];
        rb[i] = *(const float4*)&W[(size_t)(n0 + lr + i * 16) * K + k0 + lc];
    }
    if (relu_a) {
        #pragma unroll
        for (int i = 0; i < 4; i++) {
            ra[i].x = fmaxf(ra[i].x, 0.f); ra[i].y = fmaxf(ra[i].y, 0.f);
            ra[i].z = fmaxf(ra[i].z, 0.f); ra[i].w = fmaxf(ra[i].w, 0.f);
        }
    }

    const int NT = kspan >> 5;
    for (int kt = 0; kt < NT; kt++) {
        const int cur = kt & 1;
        #pragma unroll
        for (int i = 0; i < 4; i++) {
            *(float4*)&As[cur][(lr + i * 16) * TLD + lc] = ra[i];
            *(float4*)&Bs[cur][(lr + i * 16) * TLD + lc] = rb[i];
        }
        __syncthreads();
        if (kt + 1 < NT) {
            const int ko = k0 + (kt + 1) * 32 + lc;
            #pragma unroll
            for (int i = 0; i < 4; i++) {
                ra[i] = *(const float4*)&A[(size_t)(m0 + lr + i * 16) * K + ko];
                rb[i] = *(const float4*)&W[(size_t)(n0 + lr + i * 16) * K + ko];
            }
            if (relu_a) {
                #pragma unroll
                for (int i = 0; i < 4; i++) {
                    ra[i].x = fmaxf(ra[i].x, 0.f); ra[i].y = fmaxf(ra[i].y, 0.f);
                    ra[i].z = fmaxf(ra[i].z, 0.f); ra[i].w = fmaxf(ra[i].w, 0.f);
                }
            }
        }
        #pragma unroll
        for (int kk = 0; kk < 4; kk++) {
            wmma::fragment<wmma::matrix_a, 16, 16, 8, wmma::precision::tf32, wmma::row_major> a[2];
            wmma::fragment<wmma::matrix_b, 16, 16, 8, wmma::precision::tf32, wmma::col_major> bf[2];
            #pragma unroll
            for (int i = 0; i < 2; i++) {
                wmma::load_matrix_sync(a[i], &As[cur][(wm * 32 + i * 16) * TLD + kk * 8], TLD);
                #pragma unroll
                for (int t = 0; t < a[i].num_elements; t++)
                    a[i].x[t] = wmma::__float_to_tf32(a[i].x[t]);
            }
            #pragma unroll
            for (int j = 0; j < 2; j++) {
                wmma::load_matrix_sync(bf[j], &Bs[cur][(wn * 32 + j * 16) * TLD + kk * 8], TLD);
                #pragma unroll
                for (int t = 0; t < bf[j].num_elements; t++)
                    bf[j].x[t] = wmma::__float_to_tf32(bf[j].x[t]);
            }
            #pragma unroll
            for (int i = 0; i < 2; i++)
                #pragma unroll
                for (int j = 0; j < 2; j++)
                    wmma::mma_sync(c[i][j], a[i], bf[j], c[i][j]);
        }
    }

    __syncthreads();   // protect As before reuse as Cs
    float* Cs = (float*)As;
    #pragma unroll
    for (int i = 0; i < 2; i++)
        #pragma unroll
        for (int j = 0; j < 2; j++)
            wmma::store_matrix_sync(&Cs[(wm * 32 + i * 16) * TLDC + wn * 32 + j * 16],
                                    c[i][j], TLDC, wmma::mem_row_major);
    __syncthreads();
    for (int i = tid; i < 64 * 64; i += 128) {
        const int mm = i >> 6, nn = i & 63;
        atomicAdd(&C[(size_t)(m0 + mm) * N + n0 + nn], Cs[mm * TLDC + nn]);
    }
}

// ====================================================================
// K4: GRU gates
// ====================================================================
__global__ void gru_gate_kernel(const float* __restrict__ gx,
                                const float* __restrict__ gh,
                                const float* __restrict__ hidden,
                                float* __restrict__ hout) {
    const int idx = blockIdx.x * blockDim.x + threadIdx.x;
    const int b = idx >> 10, j = idx & (H_ - 1);
    const float* gxb = gx + b * 3 * H_;
    const float* ghb = gh + b * 3 * H_;
    const float xr = gxb[j],          hr = ghb[j];
    const float xz = gxb[H_ + j],     hz = ghb[H_ + j];
    const float xn = gxb[2 * H_ + j], hn = ghb[2 * H_ + j];
    const float r = 1.0f / (1.0f + expf(-(xr + hr)));
    const float z = 1.0f / (1.0f + expf(-(xz + hz)));
    const float n = tanhf(xn + r * hn);
    hout[idx] = (1.0f - z) * n + z * hidden[idx];
}

// ====================================================================
// K5: bf16 vocab GEMM  logits[B,V] = h_new[B,H] @ out_w[V,H]^T
// BM=256 (W streamed ONCE), BN=128, BK=32
// 512 threads = 16 warps (4x4), warp tile 64x32, double-buffered,
// SINGLE sync per k-iter  —  289us-validated configuration, untouched
// ====================================================================
#define VLD 40                       // bf16 leading dim (80B rows)
#define VAS_STAGE (256 * VLD)        // elems per A stage
#define VBS_STAGE (128 * VLD)        // elems per B stage
#define VOC_SMEM ((2 * VAS_STAGE + 2 * VBS_STAGE) * 2)   // bytes = 61440

__global__ __launch_bounds__(512)
void gemm_bf16_vocab(const float* __restrict__ A,
                     const float* __restrict__ W,
                     float* __restrict__ C) {
    extern __shared__ __align__(16) __nv_bfloat16 sm[];
    __nv_bfloat16* As = sm;                     // [2][256*VLD]
    __nv_bfloat16* Bs = sm + 2 * VAS_STAGE;     // [2][128*VLD]

    const int n0 = blockIdx.x * 128;
    const int tid = threadIdx.x;
    const int warp = tid >> 5;
    const int wm = warp >> 2;        // 0..3 (64 rows each)
    const int wn = warp & 3;         // 0..3 (32 cols each)
    const int lr = tid >> 3;         // 0..63
    const int lc = (tid & 7) * 4;    // 0..28

    wmma::fragment<wmma::accumulator, 16, 16, 16, float> c[4][2];
    #pragma unroll
    for (int i = 0; i < 4; i++)
        #pragma unroll
        for (int j = 0; j < 2; j++) wmma::fill_fragment(c[i][j], 0.0f);

    float4 ra[4], rb[2];
    #pragma unroll
    for (int i = 0; i < 4; i++)
        ra[i] = *(const float4*)&A[(size_t)(lr + i * 64) * H_ + lc];
    #pragma unroll
    for (int i = 0; i < 2; i++)
        rb[i] = *(const float4*)&W[(size_t)(n0 + lr + i * 64) * H_ + lc];

    const int NT = H_ / 32;   // 32
    for (int kt = 0; kt < NT; kt++) {
        const int cur = kt & 1;
        #pragma unroll
        for (int i = 0; i < 4; i++)
            *(uint2*)&As[cur * VAS_STAGE + (lr + i * 64) * VLD + lc] = cvt_f4_bf16(ra[i]);
        #pragma unroll
        for (int i = 0; i < 2; i++)
            *(uint2*)&Bs[cur * VBS_STAGE + (lr + i * 64) * VLD + lc] = cvt_f4_bf16(rb[i]);
        __syncthreads();
        if (kt + 1 < NT) {
            const int ko = (kt + 1) * 32 + lc;
            #pragma unroll
            for (int i = 0; i < 4; i++)
                ra[i] = *(const float4*)&A[(size_t)(lr + i * 64) * H_ + ko];
            #pragma unroll
            for (int i = 0; i < 2; i++)
                rb[i] = *(const float4*)&W[(size_t)(n0 + lr + i * 64) * H_ + ko];
        }
        const __nv_bfloat16* Ac = As + cur * VAS_STAGE;
        const __nv_bfloat16* Bc = Bs + cur * VBS_STAGE;
        #pragma unroll
        for (int kk = 0; kk < 2; kk++) {
            wmma::fragment<wmma::matrix_a, 16, 16, 16, __nv_bfloat16, wmma::row_major> a[4];
            wmma::fragment<wmma::matrix_b, 16, 16, 16, __nv_bfloat16, wmma::col_major> bf[2];
            #pragma unroll
            for (int i = 0; i < 4; i++)
                wmma::load_matrix_sync(a[i], &Ac[(wm * 64 + i * 16) * VLD + kk * 16], VLD);
            #pragma unroll
            for (int j = 0; j < 2; j++)
                wmma::load_matrix_sync(bf[j], &Bc[(wn * 32 + j * 16) * VLD + kk * 16], VLD);
            #pragma unroll
            for (int i = 0; i < 4; i++)
                #pragma unroll
                for (int j = 0; j < 2; j++)
                    wmma::mma_sync(c[i][j], a[i], bf[j], c[i][j]);
        }
    }

    #pragma unroll
    for (int i = 0; i < 4; i++)
        #pragma unroll
        for (int j = 0; j < 2; j++)
            wmma::store_matrix_sync(&C[(size_t)(wm * 64 + i * 16) * V_ + n0 + wn * 32 + j * 16],
                                    c[i][j], V_, wmma::mem_row_major);
}

// ====================================================================
// K6: bias + log_softmax (row in registers)
// ====================================================================
__global__ __launch_bounds__(1024)
void logsoftmax_kernel(float* __restrict__ logits,
                       const float* __restrict__ ob) {
    __shared__ float sred[32];
    const int b = blockIdx.x;
    const int tid = threadIdx.x;
    const int lane = tid & 31, wid = tid >> 5;
    float* row = logits + (size_t)b * V_;

    float v[32];
    float m = -1e30f;
    #pragma unroll
    for (int k = 0; k < 32; k++) {
        const int idx = k * 1024 + tid;
        float t = -1e30f;
        if (idx < V_) t = row[idx] + ob[idx];
        v[k] = t;
        m = fmaxf(m, t);
    }
    #pragma unroll
    for (int o = 16; o; o >>= 1) m = fmaxf(m, __shfl_xor_sync(0xffffffffu, m, o));
    if (lane == 0) sred[wid] = m;
    __syncthreads();
    if (wid == 0) {
        float t = sred[lane];
        #pragma unroll
        for (int o = 16; o; o >>= 1) t = fmaxf(t, __shfl_xor_sync(0xffffffffu, t, o));
        if (lane == 0) sred[0] = t;
    }
    __syncthreads();
    m = sred[0];
    __syncthreads();

    float s = 0.f;
    #pragma unroll
    for (int k = 0; k < 32; k++) {
        const int idx = k * 1024 + tid;
        if (idx < V_) {
            v[k] = v[k] - m;
            s += expf(v[k]);
        }
    }
    #pragma unroll
    for (int o = 16; o; o >>= 1) s += __shfl_xor_sync(0xffffffffu, s, o);
    if (lane == 0) sred[wid] = s;
    __syncthreads();
    if (wid == 0) {
        float t = sred[lane];
        #pragma unroll
        for (int o = 16; o; o >>= 1) t += __shfl_xor_sync(0xffffffffu, t, o);
        if (lane == 0) sred[0] = t;
    }
    __syncthreads();
    const float lse = logf(sred[0]);

    #pragma unroll
    for (int k = 0; k < 32; k++) {
        const int idx = k * 1024 + tid;
        if (idx < V_) row[idx] = v[k] - lse;
    }
}

// ====================================================================
extern "C" void kernel_launch(void* const* d_in, const int* in_sizes, int n_in,
                              void* d_out, int out_size) {
    const int*   ids    = (const int*)  d_in[0];
    const float* hidden = (const float*)d_in[1];
    const float* enc    = (const float*)d_in[2];
    const float* emb    = (const float*)d_in[3];
    const float* attn_w = (const float*)d_in[4];
    const float* attn_b = (const float*)d_in[5];
    const float* comb_w = (const float*)d_in[6];
    const float* comb_b = (const float*)d_in[7];
    const float* w_ih   = (const float*)d_in[8];
    const float* b_ih   = (const float*)d_in[9];
    const float* w_hh   = (const float*)d_in[10];
    const float* b_hh   = (const float*)d_in[11];
    const float* out_w  = (const float*)d_in[12];
    const float* out_b  = (const float*)d_in[13];

    float* out      = (float*)d_out;
    float* out_logp = out;
    float* out_h    = out + OFF_H;
    float* out_attn = out + OFF_ATTN;

    float *xcat, *x, *gx, *gh;
    cudaGetSymbolAddress((void**)&xcat, g_xcat);
    cudaGetSymbolAddress((void**)&x,    g_x);
    cudaGetSymbolAddress((void**)&gx,   g_gx);
    cudaGetSymbolAddress((void**)&gh,   g_gh);

    cudaFuncSetAttribute(gemm_bf16_vocab,
                         cudaFuncAttributeMaxDynamicSharedMemorySize, VOC_SMEM);

    // Side stream + events created once (first call is the uncaptured
    // correctness run; subsequent captures reuse them -> graph branches).
    static cudaStream_t s_side = nullptr;
    static cudaEvent_t ev_init = nullptr, ev_gh = nullptr;
    if (!s_side) {
        cudaStreamCreateWithFlags(&s_side, cudaStreamNonBlocking);
        cudaEventCreateWithFlags(&ev_init, cudaEventDisableTiming);
        cudaEventCreateWithFlags(&ev_gh,   cudaEventDisableTiming);
    }

    // main: init biases (writes gh, gx, x)
    init_bias_kernel<<<B_ * 3 * H_ / 256, 256>>>(gh, b_hh, gx, b_ih, x, comb_b);
    cudaEventRecord(ev_init, 0);

    // side branch: gh += hidden @ w_hh^T  (independent of attn/comb/gx)
    cudaStreamWaitEvent(s_side, ev_init, 0);
    gemm_tf32_splitk<<<dim3(48, 4, 8), 128, 0, s_side>>>(hidden, w_hh, gh, H_, 128, 3 * H_, 0);
    cudaEventRecord(ev_gh, s_side);

    // main chain: attn -> comb -> gx  (runs concurrently with gh)
    attn_kernel<<<B_, 256>>>(ids, hidden, enc, emb, attn_w, attn_b, out_attn, xcat);
    gemm_tf32_splitk<<<dim3(16, 4, 16), 128>>>(xcat, comb_w, x, 2 * H_, 128, H_, 0);
    gemm_tf32_splitk<<<dim3(48, 4, 8), 128>>>(x, w_ih, gx, H_, 128, 3 * H_, 1);

    // join: gru needs gx (main) and gh (side)
    cudaStreamWaitEvent(0, ev_gh, 0);
    gru_gate_kernel<<<B_ * H_ / 256, 256>>>(gx, gh, hidden, out_h);

    gemm_bf16_vocab<<<V_ / 128, 512, VOC_SMEM>>>(out_h, out_w, out_logp);
    logsoftmax_kernel<<<B_, 1024>>>(out_logp, out_b);
}